// round 2
// baseline (speedup 1.0000x reference)
#include <cuda_runtime.h>

// ---------------------------------------------------------------------------
// FusedLoRAAdapter: y = x @ W^T + bias + (alpha/r) * (x @ A^T) @ B^T
// Shapes: x[M,K] (M=B*S=8192, K=4096), W[N,K] (N=4096), A[R,K] (R=16),
//         B[N,R], bias[N], out[M,N]. All fp32.
//
// Kernel 1: h = x @ A^T        (tiny: 1 GFLOP; one warp per row)
// Kernel 2: out = x@W^T + bias + scale * h@B^T   (fused epilogue)
// ---------------------------------------------------------------------------

#define LORA_ALPHA 16.0f

// Scratch for h[M][R] (M=8192, R=16). Static device global: no allocation.
__device__ float g_h[8192 * 16];

// ---------------------------------------------------------------------------
// Kernel 1: LoRA down-projection. One warp per output row.
// Each lane strides the K dimension with float4; 16 accumulators per lane;
// butterfly-reduce at the end. A (256 KB) stays resident in L2.
// ---------------------------------------------------------------------------
__global__ __launch_bounds__(256) void lora_down_kernel(
    const float* __restrict__ x,
    const float* __restrict__ A,
    float* __restrict__ h,
    int M, int K, int R)
{
    int warp = (blockIdx.x * blockDim.x + threadIdx.x) >> 5;
    int lane = threadIdx.x & 31;
    if (warp >= M) return;

    const float* xr = x + (size_t)warp * K;

    float acc[16];
#pragma unroll
    for (int r = 0; r < 16; ++r) acc[r] = 0.f;

    // K is a multiple of 128 (4096). Each lane handles K/128 float4 chunks.
    for (int k = lane * 4; k < K; k += 128) {
        float4 xv = *reinterpret_cast<const float4*>(xr + k);
#pragma unroll
        for (int r = 0; r < 16; ++r) {
            float4 av = *reinterpret_cast<const float4*>(A + (size_t)r * K + k);
            acc[r] = fmaf(xv.x, av.x, acc[r]);
            acc[r] = fmaf(xv.y, av.y, acc[r]);
            acc[r] = fmaf(xv.z, av.z, acc[r]);
            acc[r] = fmaf(xv.w, av.w, acc[r]);
        }
    }

#pragma unroll
    for (int r = 0; r < 16; ++r) {
#pragma unroll
        for (int off = 16; off > 0; off >>= 1)
            acc[r] += __shfl_xor_sync(0xffffffffu, acc[r], off);
    }

    if (lane == 0) {
        float* hr = h + (size_t)warp * R;
#pragma unroll
        for (int r = 0; r < 16; ++r)
            if (r < R) hr[r] = acc[r];
    }
}

// ---------------------------------------------------------------------------
// Kernel 2: main GEMM + fused LoRA/bias epilogue.
// 128x128 block tile, BK=8, 256 threads, 8x8 per-thread micro-tile,
// double-buffered shared memory, float4 global loads (K-contiguous for both
// x and W since y = x @ W^T with both row-major).
// ---------------------------------------------------------------------------
#define BM 128
#define BN 128
#define BK 8

__global__ __launch_bounds__(256) void gemm_lora_kernel(
    const float* __restrict__ x,      // [M,K]
    const float* __restrict__ W,      // [N,K]
    const float* __restrict__ Bm,     // [N,R]
    const float* __restrict__ bias,   // [N]
    const float* __restrict__ h,      // [M,R]
    float* __restrict__ out,          // [M,N]
    int M, int N, int K, int R, float scale)
{
    __shared__ float sA[2][BK][BM];   // x tile, transposed to [k][m]
    __shared__ float sB[2][BK][BN];   // W tile, transposed to [k][n]

    const int tid = threadIdx.x;          // 0..255
    const int bm = blockIdx.y * BM;
    const int bn = blockIdx.x * BN;

    // Global load mapping: 128 rows x 8 k-cols per tile = 1024 floats.
    // 256 threads x float4 along K.
    const int lr = tid >> 1;               // 0..127: row within tile
    const int lk = (tid & 1) * 4;          // 0 or 4: k offset

    const float* xg = x + (size_t)(bm + lr) * K + lk;
    const float* wg = W + (size_t)(bn + lr) * K + lk;

    // Compute mapping: 16x16 thread grid, 8x8 outputs each.
    const int ty = (tid >> 4) * 8;         // row offset in tile
    const int tx = (tid & 15) * 8;         // col offset in tile

    float acc[8][8];
#pragma unroll
    for (int i = 0; i < 8; ++i)
#pragma unroll
        for (int j = 0; j < 8; ++j) acc[i][j] = 0.f;

    // Prologue: load tile 0 into buffer 0.
    {
        float4 av = *reinterpret_cast<const float4*>(xg);
        float4 bv = *reinterpret_cast<const float4*>(wg);
        sA[0][lk + 0][lr] = av.x; sA[0][lk + 1][lr] = av.y;
        sA[0][lk + 2][lr] = av.z; sA[0][lk + 3][lr] = av.w;
        sB[0][lk + 0][lr] = bv.x; sB[0][lk + 1][lr] = bv.y;
        sB[0][lk + 2][lr] = bv.z; sB[0][lk + 3][lr] = bv.w;
    }
    __syncthreads();

    const int nk = K / BK;
    for (int kt = 0; kt < nk; ++kt) {
        const int cur = kt & 1;
        const int nxt = cur ^ 1;

        float4 nav, nbv;
        const bool has_next = (kt + 1 < nk);
        if (has_next) {
            nav = *reinterpret_cast<const float4*>(xg + (size_t)(kt + 1) * BK);
            nbv = *reinterpret_cast<const float4*>(wg + (size_t)(kt + 1) * BK);
        }

        // Compute on current buffer.
#pragma unroll
        for (int k = 0; k < BK; ++k) {
            float a[8], b[8];
            float4 a0 = *reinterpret_cast<const float4*>(&sA[cur][k][ty]);
            float4 a1 = *reinterpret_cast<const float4*>(&sA[cur][k][ty + 4]);
            float4 b0 = *reinterpret_cast<const float4*>(&sB[cur][k][tx]);
            float4 b1 = *reinterpret_cast<const float4*>(&sB[cur][k][tx + 4]);
            a[0]=a0.x; a[1]=a0.y; a[2]=a0.z; a[3]=a0.w;
            a[4]=a1.x; a[5]=a1.y; a[6]=a1.z; a[7]=a1.w;
            b[0]=b0.x; b[1]=b0.y; b[2]=b0.z; b[3]=b0.w;
            b[4]=b1.x; b[5]=b1.y; b[6]=b1.z; b[7]=b1.w;
#pragma unroll
            for (int i = 0; i < 8; ++i)
#pragma unroll
                for (int j = 0; j < 8; ++j)
                    acc[i][j] = fmaf(a[i], b[j], acc[i][j]);
        }

        if (has_next) {
            sA[nxt][lk + 0][lr] = nav.x; sA[nxt][lk + 1][lr] = nav.y;
            sA[nxt][lk + 2][lr] = nav.z; sA[nxt][lk + 3][lr] = nav.w;
            sB[nxt][lk + 0][lr] = nbv.x; sB[nxt][lk + 1][lr] = nbv.y;
            sB[nxt][lk + 2][lr] = nbv.z; sB[nxt][lk + 3][lr] = nbv.w;
        }
        __syncthreads();
    }

    // Epilogue: out[m][n] = acc + bias[n] + scale * dot(h[m,:], B[n,:])
#pragma unroll
    for (int i = 0; i < 8; ++i) {
        const int m = bm + ty + i;
        const float* hr = h + (size_t)m * R;
        float hreg[16];
#pragma unroll
        for (int r = 0; r < 16; ++r) hreg[r] = (r < R) ? hr[r] : 0.f;

#pragma unroll
        for (int j = 0; j < 8; ++j) {
            const int n = bn + tx + j;
            const float* br = Bm + (size_t)n * R;
            float lora = 0.f;
#pragma unroll
            for (int r = 0; r < 16; ++r)
                if (r < R) lora = fmaf(hreg[r], __ldg(br + r), lora);
            out[(size_t)m * N + n] = acc[i][j] + __ldg(bias + n) + scale * lora;
        }
    }
}

// ---------------------------------------------------------------------------
// Launch
// ---------------------------------------------------------------------------
extern "C" void kernel_launch(void* const* d_in, const int* in_sizes, int n_in,
                              void* d_out, int out_size)
{
    const float* x    = (const float*)d_in[0];  // [M,K]
    const float* W    = (const float*)d_in[1];  // [N,K]
    const float* A    = (const float*)d_in[2];  // [R,K]
    const float* Bm   = (const float*)d_in[3];  // [N,R]
    const float* bias = (const float*)d_in[4];  // [N]
    float* out = (float*)d_out;

    const int N = in_sizes[4];
    const int K = in_sizes[1] / N;
    const int M = in_sizes[0] / K;
    const int R = in_sizes[2] / K;
    const float scale = LORA_ALPHA / (float)R;

    float* h = nullptr;
    cudaGetSymbolAddress((void**)&h, g_h);

    // Kernel 1: h = x @ A^T. One warp per row, 8 warps per block.
    {
        int blocks = (M + 7) / 8;
        lora_down_kernel<<<blocks, 256>>>(x, A, h, M, K, R);
    }

    // Kernel 2: fused GEMM + bias + LoRA up-projection.
    {
        dim3 grid(N / BN, M / BM);
        gemm_lora_kernel<<<grid, 256>>>(x, W, Bm, bias, h, out, M, N, K, R, scale);
    }
}

// round 4
// speedup vs baseline: 2.9197x; 2.9197x over previous
#include <cuda_runtime.h>
#include <cuda_bf16.h>
#include <cstdint>

// ============================================================================
// FusedLoRAAdapter:  y = x @ W^T + bias + (alpha/r) * (x @ A^T) @ B^T
//
// Strategy (sm_100 baseline ISA — no tcgen05 on this build):
//   1) h = x @ A^T                       (tiny fp32 kernel)
//   2) K-extension: x_ext=[x|scale*h|0], W_ext=[W|B|0], KE=4160
//   3) bf16 hi/lo split:  v = vh + vl;  y ≈ xh*wh + xh*wl + xl*wh  (fp32 acc)
//   4) GEMM via mma.sync.m16n8k16 bf16, cp.async 4-stage pipeline
// ============================================================================

#define LORA_ALPHA 16.0f

constexpr int MM = 8192, NN = 4096, KK = 4096, RR = 16;
constexpr int KE = 4160;                    // 4096 + 16 + 48 pad
constexpr int BM = 128, BN = 128, BK = 32;  // BK in bf16 elements (64 B rows)
constexpr int NKT = KE / BK;                // 130
constexpr int STAGES = 4;

// -------- scratch (static device globals; no allocation) --------
__device__ float g_h[MM * RR];
__device__ __align__(256) __nv_bfloat16 g_xh[(size_t)MM * KE];
__device__ __align__(256) __nv_bfloat16 g_xl[(size_t)MM * KE];
__device__ __align__(256) __nv_bfloat16 g_wh[(size_t)NN * KE];
__device__ __align__(256) __nv_bfloat16 g_wl[(size_t)NN * KE];

// ============================================================================
// helpers
// ============================================================================
__device__ __forceinline__ uint32_t smem_u32(const void* p) {
    uint32_t a;
    asm("{ .reg .u64 t; cvta.to.shared.u64 t, %1; cvt.u32.u64 %0, t; }"
        : "=r"(a) : "l"(p));
    return a;
}
// XOR-swizzle: chunk bits [6:4] ^= offset bits [9:7]  (64B rows, 128B lines)
__device__ __forceinline__ uint32_t swz(uint32_t o) {
    return o ^ ((o >> 3) & 0x70);
}

#define CP16(dst, src) \
    asm volatile("cp.async.cg.shared.global [%0], [%1], 16;" \
                 :: "r"(dst), "l"(src) : "memory")
#define CP_COMMIT() asm volatile("cp.async.commit_group;" ::: "memory")
#define CP_WAIT2()  asm volatile("cp.async.wait_group 2;" ::: "memory")

#define LDSM4(r, a) \
    asm volatile("ldmatrix.sync.aligned.m8n8.x4.shared.b16 {%0,%1,%2,%3}, [%4];" \
                 : "=r"((r)[0]), "=r"((r)[1]), "=r"((r)[2]), "=r"((r)[3]) \
                 : "r"(a))

__device__ __forceinline__ void mma16816(float* d, const uint32_t* a,
                                         uint32_t b0, uint32_t b1) {
    asm volatile(
        "mma.sync.aligned.m16n8k16.row.col.f32.bf16.bf16.f32 "
        "{%0,%1,%2,%3}, {%4,%5,%6,%7}, {%8,%9}, {%0,%1,%2,%3};"
        : "+f"(d[0]), "+f"(d[1]), "+f"(d[2]), "+f"(d[3])
        : "r"(a[0]), "r"(a[1]), "r"(a[2]), "r"(a[3]), "r"(b0), "r"(b1));
}

// ============================================================================
// Kernel 1: h = x @ A^T  (one warp per row)
// ============================================================================
__global__ __launch_bounds__(256) void lora_down_kernel(
    const float* __restrict__ x, const float* __restrict__ A)
{
    int warp = (blockIdx.x * blockDim.x + threadIdx.x) >> 5;
    int lane = threadIdx.x & 31;
    if (warp >= MM) return;
    const float* xr = x + (size_t)warp * KK;

    float acc[RR];
#pragma unroll
    for (int r = 0; r < RR; ++r) acc[r] = 0.f;

    for (int k = lane * 4; k < KK; k += 128) {
        float4 xv = *reinterpret_cast<const float4*>(xr + k);
#pragma unroll
        for (int r = 0; r < RR; ++r) {
            float4 av = *reinterpret_cast<const float4*>(A + (size_t)r * KK + k);
            acc[r] = fmaf(xv.x, av.x, acc[r]);
            acc[r] = fmaf(xv.y, av.y, acc[r]);
            acc[r] = fmaf(xv.z, av.z, acc[r]);
            acc[r] = fmaf(xv.w, av.w, acc[r]);
        }
    }
#pragma unroll
    for (int r = 0; r < RR; ++r)
#pragma unroll
        for (int off = 16; off > 0; off >>= 1)
            acc[r] += __shfl_xor_sync(0xffffffffu, acc[r], off);

    if (lane == 0) {
#pragma unroll
        for (int r = 0; r < RR; ++r) g_h[(size_t)warp * RR + r] = acc[r];
    }
}

// ============================================================================
// Kernels 2/3: fp32 -> bf16 hi/lo split with K-extension
// ============================================================================
__device__ __forceinline__ void split_pack4(const float* v, uint2& hiw, uint2& low) {
    unsigned short h[4], l[4];
#pragma unroll
    for (int e = 0; e < 4; ++e) {
        __nv_bfloat16 hb = __float2bfloat16(v[e]);
        float rem = v[e] - __bfloat162float(hb);
        __nv_bfloat16 lb = __float2bfloat16(rem);
        h[e] = __bfloat16_as_ushort(hb);
        l[e] = __bfloat16_as_ushort(lb);
    }
    hiw.x = (uint32_t)h[0] | ((uint32_t)h[1] << 16);
    hiw.y = (uint32_t)h[2] | ((uint32_t)h[3] << 16);
    low.x = (uint32_t)l[0] | ((uint32_t)l[1] << 16);
    low.y = (uint32_t)l[2] | ((uint32_t)l[3] << 16);
}

__global__ __launch_bounds__(256) void convert_x_kernel(
    const float* __restrict__ x, float scale)
{
    size_t idx = (size_t)blockIdx.x * blockDim.x + threadIdx.x;
    constexpr size_t GROUPS = (size_t)MM * (KE / 4);
    if (idx >= GROUPS) return;
    int m = (int)(idx / (KE / 4));
    int k = (int)(idx % (KE / 4)) * 4;

    float v[4];
    if (k < KK) {
        float4 t = *reinterpret_cast<const float4*>(x + (size_t)m * KK + k);
        v[0] = t.x; v[1] = t.y; v[2] = t.z; v[3] = t.w;
    } else if (k < KK + RR) {
        const float* hp = g_h + (size_t)m * RR + (k - KK);
        v[0] = scale * hp[0]; v[1] = scale * hp[1];
        v[2] = scale * hp[2]; v[3] = scale * hp[3];
    } else {
        v[0] = v[1] = v[2] = v[3] = 0.f;
    }
    uint2 hiw, low;
    split_pack4(v, hiw, low);
    size_t o = (size_t)m * KE + k;
    *reinterpret_cast<uint2*>(&g_xh[o]) = hiw;
    *reinterpret_cast<uint2*>(&g_xl[o]) = low;
}

__global__ __launch_bounds__(256) void convert_w_kernel(
    const float* __restrict__ W, const float* __restrict__ Bm)
{
    size_t idx = (size_t)blockIdx.x * blockDim.x + threadIdx.x;
    constexpr size_t GROUPS = (size_t)NN * (KE / 4);
    if (idx >= GROUPS) return;
    int n = (int)(idx / (KE / 4));
    int k = (int)(idx % (KE / 4)) * 4;

    float v[4];
    if (k < KK) {
        float4 t = *reinterpret_cast<const float4*>(W + (size_t)n * KK + k);
        v[0] = t.x; v[1] = t.y; v[2] = t.z; v[3] = t.w;
    } else if (k < KK + RR) {
        const float* bp = Bm + (size_t)n * RR + (k - KK);
        v[0] = bp[0]; v[1] = bp[1]; v[2] = bp[2]; v[3] = bp[3];
    } else {
        v[0] = v[1] = v[2] = v[3] = 0.f;
    }
    uint2 hiw, low;
    split_pack4(v, hiw, low);
    size_t o = (size_t)n * KE + k;
    *reinterpret_cast<uint2*>(&g_wh[o]) = hiw;
    *reinterpret_cast<uint2*>(&g_wl[o]) = low;
}

// ============================================================================
// Kernel 4: mma.sync bf16 GEMM. 128x128x32 tiles, 4-stage cp.async pipeline.
// 256 threads / 8 warps (2 m-groups x 4 n-groups), warp tile 64x32.
// Per k16 step: 3 split terms -> 48 HMMA / warp.
// ============================================================================
constexpr int TILE_B  = BM * BK * 2;       // 8192 bytes per tensor tile
constexpr int OFF_AH = 0, OFF_AL = TILE_B, OFF_BH = 2 * TILE_B, OFF_BL = 3 * TILE_B;
constexpr int STAGE_B = 4 * TILE_B;        // 32768
constexpr int GEMM_SMEM = STAGES * STAGE_B; // 131072

__global__ void __launch_bounds__(256, 1) gemm_kernel(
    const float* __restrict__ bias, float* __restrict__ out)
{
    extern __shared__ char smem[];
    const uint32_t sbase = smem_u32(smem);
    const int tid = threadIdx.x;
    const int lane = tid & 31;
    const int wid = tid >> 5;
    const int wm = wid & 1;        // 0..1  (64-row group)
    const int wn = wid >> 1;       // 0..3  (32-col group)

    // ---- 8x8 supertile rasterization for L2 reuse ----
    const int t = blockIdx.x;                 // 0..2047
    const int sb_id = t >> 6;                 // 0..31
    const int smt = sb_id & 7, snt = sb_id >> 3;
    const int lt = t & 63;
    const int bm = (smt * 8 + (lt & 7)) * BM;
    const int bn = (snt * 8 + (lt >> 3)) * BN;

    // ---- load mapping: thread -> (2 rows) x (16B chunk) per tensor ----
    const int lrow = tid >> 2;                // 0..63
    const int lc = (tid & 3) * 16;            // 0,16,32,48 (bytes in 64B row)
    const uint32_t d0 = swz((uint32_t)lrow * 64 + lc);
    const uint32_t d1 = swz((uint32_t)(lrow + 64) * 64 + lc);

    const char* pxh0 = (const char*)g_xh + ((size_t)(bm + lrow) * KE) * 2 + lc;
    const char* pxh1 = (const char*)g_xh + ((size_t)(bm + lrow + 64) * KE) * 2 + lc;
    const char* pxl0 = (const char*)g_xl + ((size_t)(bm + lrow) * KE) * 2 + lc;
    const char* pxl1 = (const char*)g_xl + ((size_t)(bm + lrow + 64) * KE) * 2 + lc;
    const char* pwh0 = (const char*)g_wh + ((size_t)(bn + lrow) * KE) * 2 + lc;
    const char* pwh1 = (const char*)g_wh + ((size_t)(bn + lrow + 64) * KE) * 2 + lc;
    const char* pwl0 = (const char*)g_wl + ((size_t)(bn + lrow) * KE) * 2 + lc;
    const char* pwl1 = (const char*)g_wl + ((size_t)(bn + lrow + 64) * KE) * 2 + lc;

    float acc[4][4][4];
#pragma unroll
    for (int i = 0; i < 4; ++i)
#pragma unroll
        for (int j = 0; j < 4; ++j)
#pragma unroll
            for (int e = 0; e < 4; ++e) acc[i][j][e] = 0.f;

    // fragment addresses (constant per thread, vary by stage/ks)
    const int ar = lane & 15;                 // row within 16-row A tile
    const int ah_half = (lane >> 4) * 16;     // 0 or 16 bytes (k half)
    const int brow = wn * 32 + lane;          // B row for ldsm.x4

    auto load_stage = [&](int kt, int s) {
        const uint32_t st = sbase + s * STAGE_B;
        const size_t ko = (size_t)kt * 64;    // 32 bf16 = 64 bytes
        CP16(st + OFF_AH + d0, pxh0 + ko);
        CP16(st + OFF_AH + d1, pxh1 + ko);
        CP16(st + OFF_AL + d0, pxl0 + ko);
        CP16(st + OFF_AL + d1, pxl1 + ko);
        CP16(st + OFF_BH + d0, pwh0 + ko);
        CP16(st + OFF_BH + d1, pwh1 + ko);
        CP16(st + OFF_BL + d0, pwl0 + ko);
        CP16(st + OFF_BL + d1, pwl1 + ko);
    };

    // prologue: stages 0..STAGES-2
#pragma unroll
    for (int s = 0; s < STAGES - 1; ++s) {
        load_stage(s, s);
        CP_COMMIT();
    }

    for (int kt = 0; kt < NKT; ++kt) {
        CP_WAIT2();
        __syncthreads();

        const int nk = kt + STAGES - 1;
        if (nk < NKT) load_stage(nk, nk & (STAGES - 1));
        CP_COMMIT();

        const uint32_t st = sbase + (kt & (STAGES - 1)) * STAGE_B;

#pragma unroll
        for (int ks = 0; ks < 2; ++ks) {
            const int kb = ks * 32;           // byte base of this k16
            uint32_t ah[4][4], al[4][4];
#pragma unroll
            for (int mt = 0; mt < 4; ++mt) {
                const uint32_t ro = (uint32_t)(wm * 64 + mt * 16 + ar) * 64;
                LDSM4(ah[mt], st + OFF_AH + swz(ro + kb + ah_half));
                LDSM4(al[mt], st + OFF_AL + swz(ro + kb + ah_half));
            }
            uint32_t bh0[4], bh1[4], bl0[4], bl1[4];
            {
                const uint32_t ro = (uint32_t)brow * 64;
                LDSM4(bh0, st + OFF_BH + swz(ro + kb));
                LDSM4(bh1, st + OFF_BH + swz(ro + kb + 16));
                LDSM4(bl0, st + OFF_BL + swz(ro + kb));
                LDSM4(bl1, st + OFF_BL + swz(ro + kb + 16));
            }
            // term 1: xh * wh
#pragma unroll
            for (int mt = 0; mt < 4; ++mt)
#pragma unroll
                for (int nt = 0; nt < 4; ++nt)
                    mma16816(acc[mt][nt], ah[mt], bh0[nt], bh1[nt]);
            // term 2: xh * wl
#pragma unroll
            for (int mt = 0; mt < 4; ++mt)
#pragma unroll
                for (int nt = 0; nt < 4; ++nt)
                    mma16816(acc[mt][nt], ah[mt], bl0[nt], bl1[nt]);
            // term 3: xl * wh
#pragma unroll
            for (int mt = 0; mt < 4; ++mt)
#pragma unroll
                for (int nt = 0; nt < 4; ++nt)
                    mma16816(acc[mt][nt], al[mt], bh0[nt], bh1[nt]);
        }
        __syncthreads();
    }

    // ---- epilogue: acc + bias -> out ----
    const int g = lane >> 2;       // 0..7
    const int j = (lane & 3) * 2;  // 0,2,4,6
#pragma unroll
    for (int mt = 0; mt < 4; ++mt) {
#pragma unroll
        for (int nt = 0; nt < 4; ++nt) {
            const int m0 = bm + wm * 64 + mt * 16 + g;
            const int n0 = bn + wn * 32 + nt * 8 + j;
            const float b0 = __ldg(bias + n0);
            const float b1 = __ldg(bias + n0 + 1);
            float2 v0 = make_float2(acc[mt][nt][0] + b0, acc[mt][nt][1] + b1);
            float2 v1 = make_float2(acc[mt][nt][2] + b0, acc[mt][nt][3] + b1);
            *reinterpret_cast<float2*>(out + (size_t)m0 * NN + n0) = v0;
            *reinterpret_cast<float2*>(out + (size_t)(m0 + 8) * NN + n0) = v1;
        }
    }
}

// ============================================================================
// Launch
// ============================================================================
extern "C" void kernel_launch(void* const* d_in, const int* in_sizes, int n_in,
                              void* d_out, int out_size)
{
    const float* x    = (const float*)d_in[0];  // [M,K]
    const float* W    = (const float*)d_in[1];  // [N,K]
    const float* A    = (const float*)d_in[2];  // [R,K]
    const float* Bm   = (const float*)d_in[3];  // [N,R]
    const float* bias = (const float*)d_in[4];  // [N]
    float* out = (float*)d_out;

    const float scale = LORA_ALPHA / (float)RR;

    cudaFuncSetAttribute(gemm_kernel,
                         cudaFuncAttributeMaxDynamicSharedMemorySize, GEMM_SMEM);

    // 1) h = x @ A^T
    lora_down_kernel<<<(MM + 7) / 8, 256>>>(x, A);

    // 2) split x (+scale*h, +pad)
    {
        size_t groups = (size_t)MM * (KE / 4);
        convert_x_kernel<<<(unsigned)((groups + 255) / 256), 256>>>(x, scale);
    }
    // 3) split W (+B, +pad)
    {
        size_t groups = (size_t)NN * (KE / 4);
        convert_w_kernel<<<(unsigned)((groups + 255) / 256), 256>>>(W, Bm);
    }
    // 4) GEMM + bias epilogue
    gemm_kernel<<<2048, 256, GEMM_SMEM>>>(bias, out);
}

// round 5
// speedup vs baseline: 4.7264x; 1.6188x over previous
#include <cuda_runtime.h>
#include <cuda_fp16.h>
#include <cstdint>

// ============================================================================
// FusedLoRAAdapter:  y = x @ W^T + bias + (alpha/r) * (x @ A^T) @ B^T
//
// sm_100 baseline ISA (no tcgen05 on this build target).
//   1) h = x @ A^T                          (tiny fp32 kernel)
//   2) K-extension: x_ext=[x|scale*h|0], W_ext=[W|B|0], KE=4160
//   3) fp16 split of x: x = xh + xl (exact to ~2^-22); W single fp16.
//      y ≈ xh@wh + xl@wh   (fp32 accum; error ~2.8e-4 rms < 1e-3)
//   4) GEMM via mma.sync.m16n8k16.f16, 4-stage cp.async, 2 CTAs/SM
// ============================================================================

#define LORA_ALPHA 16.0f

constexpr int MM = 8192, NN = 4096, KK = 4096, RR = 16;
constexpr int KE = 4160;                    // 4096 + 16 + 48 pad
constexpr int BM = 128, BN = 128, BK = 32;  // BK in fp16 elements (64 B rows)
constexpr int NKT = KE / BK;                // 130
constexpr int STAGES = 4;

// -------- scratch (static device globals; no allocation) --------
__device__ float g_h[MM * RR];
__device__ __align__(256) __half g_xh[(size_t)MM * KE];
__device__ __align__(256) __half g_xl[(size_t)MM * KE];
__device__ __align__(256) __half g_wh[(size_t)NN * KE];

// ============================================================================
// helpers
// ============================================================================
__device__ __forceinline__ uint32_t smem_u32(const void* p) {
    uint32_t a;
    asm("{ .reg .u64 t; cvta.to.shared.u64 t, %1; cvt.u32.u64 %0, t; }"
        : "=r"(a) : "l"(p));
    return a;
}
// XOR-swizzle for 64B rows packed in 128B lines: bits [6:4] ^= bits [9:7]
__device__ __forceinline__ uint32_t swz(uint32_t o) {
    return o ^ ((o >> 3) & 0x70);
}

#define CP16(dst, src) \
    asm volatile("cp.async.cg.shared.global [%0], [%1], 16;" \
                 :: "r"(dst), "l"(src) : "memory")
#define CP_COMMIT() asm volatile("cp.async.commit_group;" ::: "memory")
#define CP_WAIT2()  asm volatile("cp.async.wait_group 2;" ::: "memory")

#define LDSM4(r, a) \
    asm volatile("ldmatrix.sync.aligned.m8n8.x4.shared.b16 {%0,%1,%2,%3}, [%4];" \
                 : "=r"((r)[0]), "=r"((r)[1]), "=r"((r)[2]), "=r"((r)[3]) \
                 : "r"(a))

__device__ __forceinline__ void mma16816(float* d, const uint32_t* a,
                                         uint32_t b0, uint32_t b1) {
    asm volatile(
        "mma.sync.aligned.m16n8k16.row.col.f32.f16.f16.f32 "
        "{%0,%1,%2,%3}, {%4,%5,%6,%7}, {%8,%9}, {%0,%1,%2,%3};"
        : "+f"(d[0]), "+f"(d[1]), "+f"(d[2]), "+f"(d[3])
        : "r"(a[0]), "r"(a[1]), "r"(a[2]), "r"(a[3]), "r"(b0), "r"(b1));
}

// ============================================================================
// Kernel 1: h = x @ A^T  (one warp per row)
// ============================================================================
__global__ __launch_bounds__(256) void lora_down_kernel(
    const float* __restrict__ x, const float* __restrict__ A)
{
    int warp = (blockIdx.x * blockDim.x + threadIdx.x) >> 5;
    int lane = threadIdx.x & 31;
    if (warp >= MM) return;
    const float* xr = x + (size_t)warp * KK;

    float acc[RR];
#pragma unroll
    for (int r = 0; r < RR; ++r) acc[r] = 0.f;

    for (int k = lane * 4; k < KK; k += 128) {
        float4 xv = *reinterpret_cast<const float4*>(xr + k);
#pragma unroll
        for (int r = 0; r < RR; ++r) {
            float4 av = *reinterpret_cast<const float4*>(A + (size_t)r * KK + k);
            acc[r] = fmaf(xv.x, av.x, acc[r]);
            acc[r] = fmaf(xv.y, av.y, acc[r]);
            acc[r] = fmaf(xv.z, av.z, acc[r]);
            acc[r] = fmaf(xv.w, av.w, acc[r]);
        }
    }
#pragma unroll
    for (int r = 0; r < RR; ++r)
#pragma unroll
        for (int off = 16; off > 0; off >>= 1)
            acc[r] += __shfl_xor_sync(0xffffffffu, acc[r], off);

    if (lane == 0) {
#pragma unroll
        for (int r = 0; r < RR; ++r) g_h[(size_t)warp * RR + r] = acc[r];
    }
}

// ============================================================================
// Kernels 2/3: fp32 -> fp16 conversion with K-extension
// ============================================================================
__global__ __launch_bounds__(256) void convert_x_kernel(
    const float* __restrict__ x, float scale)
{
    size_t idx = (size_t)blockIdx.x * blockDim.x + threadIdx.x;
    constexpr size_t GROUPS = (size_t)MM * (KE / 4);
    if (idx >= GROUPS) return;
    int m = (int)(idx / (KE / 4));
    int k = (int)(idx % (KE / 4)) * 4;

    float v[4];
    if (k < KK) {
        float4 t = *reinterpret_cast<const float4*>(x + (size_t)m * KK + k);
        v[0] = t.x; v[1] = t.y; v[2] = t.z; v[3] = t.w;
    } else if (k < KK + RR) {
        const float* hp = g_h + (size_t)m * RR + (k - KK);
        v[0] = scale * hp[0]; v[1] = scale * hp[1];
        v[2] = scale * hp[2]; v[3] = scale * hp[3];
    } else {
        v[0] = v[1] = v[2] = v[3] = 0.f;
    }
    unsigned short h[4], l[4];
#pragma unroll
    for (int e = 0; e < 4; ++e) {
        __half hb = __float2half_rn(v[e]);
        float rem = v[e] - __half2float(hb);
        __half lb = __float2half_rn(rem);
        h[e] = __half_as_ushort(hb);
        l[e] = __half_as_ushort(lb);
    }
    uint2 hiw, low;
    hiw.x = (uint32_t)h[0] | ((uint32_t)h[1] << 16);
    hiw.y = (uint32_t)h[2] | ((uint32_t)h[3] << 16);
    low.x = (uint32_t)l[0] | ((uint32_t)l[1] << 16);
    low.y = (uint32_t)l[2] | ((uint32_t)l[3] << 16);
    size_t o = (size_t)m * KE + k;
    *reinterpret_cast<uint2*>(&g_xh[o]) = hiw;
    *reinterpret_cast<uint2*>(&g_xl[o]) = low;
}

__global__ __launch_bounds__(256) void convert_w_kernel(
    const float* __restrict__ W, const float* __restrict__ Bm)
{
    size_t idx = (size_t)blockIdx.x * blockDim.x + threadIdx.x;
    constexpr size_t GROUPS = (size_t)NN * (KE / 4);
    if (idx >= GROUPS) return;
    int n = (int)(idx / (KE / 4));
    int k = (int)(idx % (KE / 4)) * 4;

    float v[4];
    if (k < KK) {
        float4 t = *reinterpret_cast<const float4*>(W + (size_t)n * KK + k);
        v[0] = t.x; v[1] = t.y; v[2] = t.z; v[3] = t.w;
    } else if (k < KK + RR) {
        const float* bp = Bm + (size_t)n * RR + (k - KK);
        v[0] = bp[0]; v[1] = bp[1]; v[2] = bp[2]; v[3] = bp[3];
    } else {
        v[0] = v[1] = v[2] = v[3] = 0.f;
    }
    unsigned short h[4];
#pragma unroll
    for (int e = 0; e < 4; ++e) h[e] = __half_as_ushort(__float2half_rn(v[e]));
    uint2 hw;
    hw.x = (uint32_t)h[0] | ((uint32_t)h[1] << 16);
    hw.y = (uint32_t)h[2] | ((uint32_t)h[3] << 16);
    *reinterpret_cast<uint2*>(&g_wh[(size_t)n * KE + k]) = hw;
}

// ============================================================================
// Kernel 4: mma.sync fp16 GEMM. 128x128x32 tiles, 4-stage cp.async pipeline.
// 256 threads / 8 warps (2 m-groups x 4 n-groups), warp tile 64x32.
// Per k16 step: 2 split terms -> 32 HMMA / warp, 10 LDSM.x4 / warp.
// 2 CTAs/SM (96 KB smem, <=128 regs).
// ============================================================================
constexpr int TILE_B  = BM * BK * 2;       // 8192 bytes per tensor tile
constexpr int OFF_AH = 0, OFF_AL = TILE_B, OFF_BH = 2 * TILE_B;
constexpr int STAGE_B = 3 * TILE_B;        // 24576
constexpr int GEMM_SMEM = STAGES * STAGE_B; // 98304

__global__ void __launch_bounds__(256, 2) gemm_kernel(
    const float* __restrict__ bias, float* __restrict__ out)
{
    extern __shared__ char smem[];
    const uint32_t sbase = smem_u32(smem);
    const int tid = threadIdx.x;
    const int lane = tid & 31;
    const int wid = tid >> 5;
    const int wm = wid & 1;        // 0..1  (64-row group)
    const int wn = wid >> 1;       // 0..3  (32-col group)

    // ---- 8x8 supertile rasterization for L2 reuse ----
    const int t = blockIdx.x;                 // 0..2047
    const int sb_id = t >> 6;                 // 0..31
    const int smt = sb_id & 7, snt = sb_id >> 3;
    const int lt = t & 63;
    const int bm = (smt * 8 + (lt & 7)) * BM;
    const int bn = (snt * 8 + (lt >> 3)) * BN;

    // ---- load mapping: thread -> (2 rows) x (16B chunk) per tensor ----
    const int lrow = tid >> 2;                // 0..63
    const int lc = (tid & 3) * 16;            // 0,16,32,48 (bytes in 64B row)
    const uint32_t d0 = swz((uint32_t)lrow * 64 + lc);
    const uint32_t d1 = swz((uint32_t)(lrow + 64) * 64 + lc);

    const char* pxh0 = (const char*)g_xh + ((size_t)(bm + lrow) * KE) * 2 + lc;
    const char* pxh1 = (const char*)g_xh + ((size_t)(bm + lrow + 64) * KE) * 2 + lc;
    const char* pxl0 = (const char*)g_xl + ((size_t)(bm + lrow) * KE) * 2 + lc;
    const char* pxl1 = (const char*)g_xl + ((size_t)(bm + lrow + 64) * KE) * 2 + lc;
    const char* pwh0 = (const char*)g_wh + ((size_t)(bn + lrow) * KE) * 2 + lc;
    const char* pwh1 = (const char*)g_wh + ((size_t)(bn + lrow + 64) * KE) * 2 + lc;

    float acc[4][4][4];
#pragma unroll
    for (int i = 0; i < 4; ++i)
#pragma unroll
        for (int j = 0; j < 4; ++j)
#pragma unroll
            for (int e = 0; e < 4; ++e) acc[i][j][e] = 0.f;

    const int ar = lane & 15;                 // row within 16-row A tile
    const int ah_half = (lane >> 4) * 16;     // 0 or 16 bytes (k half)
    const int brow = wn * 32 + lane;          // B row for ldsm.x4

    auto load_stage = [&](int kt, int s) {
        const uint32_t st = sbase + s * STAGE_B;
        const size_t ko = (size_t)kt * 64;    // 32 fp16 = 64 bytes
        CP16(st + OFF_AH + d0, pxh0 + ko);
        CP16(st + OFF_AH + d1, pxh1 + ko);
        CP16(st + OFF_AL + d0, pxl0 + ko);
        CP16(st + OFF_AL + d1, pxl1 + ko);
        CP16(st + OFF_BH + d0, pwh0 + ko);
        CP16(st + OFF_BH + d1, pwh1 + ko);
    };

    // prologue: stages 0..STAGES-2
#pragma unroll
    for (int s = 0; s < STAGES - 1; ++s) {
        load_stage(s, s);
        CP_COMMIT();
    }

    for (int kt = 0; kt < NKT; ++kt) {
        CP_WAIT2();
        __syncthreads();

        const int nk = kt + STAGES - 1;
        if (nk < NKT) load_stage(nk, nk & (STAGES - 1));
        CP_COMMIT();

        const uint32_t st = sbase + (kt & (STAGES - 1)) * STAGE_B;

#pragma unroll
        for (int ks = 0; ks < 2; ++ks) {
            const int kb = ks * 32;           // byte base of this k16
            uint32_t ah[4][4], al[4][4];
#pragma unroll
            for (int mt = 0; mt < 4; ++mt) {
                const uint32_t ro = (uint32_t)(wm * 64 + mt * 16 + ar) * 64;
                LDSM4(ah[mt], st + OFF_AH + swz(ro + kb + ah_half));
                LDSM4(al[mt], st + OFF_AL + swz(ro + kb + ah_half));
            }
            uint32_t bh0[4], bh1[4];
            {
                const uint32_t ro = (uint32_t)brow * 64;
                LDSM4(bh0, st + OFF_BH + swz(ro + kb));
                LDSM4(bh1, st + OFF_BH + swz(ro + kb + 16));
            }
            // term 1: xh * wh
#pragma unroll
            for (int mt = 0; mt < 4; ++mt)
#pragma unroll
                for (int nt = 0; nt < 4; ++nt)
                    mma16816(acc[mt][nt], ah[mt], bh0[nt], bh1[nt]);
            // term 2: xl * wh
#pragma unroll
            for (int mt = 0; mt < 4; ++mt)
#pragma unroll
                for (int nt = 0; nt < 4; ++nt)
                    mma16816(acc[mt][nt], al[mt], bh0[nt], bh1[nt]);
        }
        // NOTE: no trailing __syncthreads needed — the top barrier of the
        // next iteration orders stage reuse (write distance = STAGES-1 > 0).
    }

    // ---- epilogue: acc + bias -> out ----
    const int g = lane >> 2;       // 0..7
    const int j = (lane & 3) * 2;  // 0,2,4,6
#pragma unroll
    for (int mt = 0; mt < 4; ++mt) {
#pragma unroll
        for (int nt = 0; nt < 4; ++nt) {
            const int m0 = bm + wm * 64 + mt * 16 + g;
            const int n0 = bn + wn * 32 + nt * 8 + j;
            const float b0 = __ldg(bias + n0);
            const float b1 = __ldg(bias + n0 + 1);
            float2 v0 = make_float2(acc[mt][nt][0] + b0, acc[mt][nt][1] + b1);
            float2 v1 = make_float2(acc[mt][nt][2] + b0, acc[mt][nt][3] + b1);
            *reinterpret_cast<float2*>(out + (size_t)m0 * NN + n0) = v0;
            *reinterpret_cast<float2*>(out + (size_t)(m0 + 8) * NN + n0) = v1;
        }
    }
}

// ============================================================================
// Launch
// ============================================================================
extern "C" void kernel_launch(void* const* d_in, const int* in_sizes, int n_in,
                              void* d_out, int out_size)
{
    const float* x    = (const float*)d_in[0];  // [M,K]
    const float* W    = (const float*)d_in[1];  // [N,K]
    const float* A    = (const float*)d_in[2];  // [R,K]
    const float* Bm   = (const float*)d_in[3];  // [N,R]
    const float* bias = (const float*)d_in[4];  // [N]
    float* out = (float*)d_out;

    const float scale = LORA_ALPHA / (float)RR;

    cudaFuncSetAttribute(gemm_kernel,
                         cudaFuncAttributeMaxDynamicSharedMemorySize, GEMM_SMEM);

    // 1) h = x @ A^T
    lora_down_kernel<<<(MM + 7) / 8, 256>>>(x, A);

    // 2) split x (+scale*h, +pad) into fp16 hi/lo
    {
        size_t groups = (size_t)MM * (KE / 4);
        convert_x_kernel<<<(unsigned)((groups + 255) / 256), 256>>>(x, scale);
    }
    // 3) round W (+B, +pad) to fp16
    {
        size_t groups = (size_t)NN * (KE / 4);
        convert_w_kernel<<<(unsigned)((groups + 255) / 256), 256>>>(W, Bm);
    }
    // 4) GEMM + bias epilogue
    gemm_kernel<<<2048, 256, GEMM_SMEM>>>(bias, out);
}

// round 6
// speedup vs baseline: 6.6953x; 1.4166x over previous
#include <cuda_runtime.h>
#include <cuda_fp16.h>
#include <cstdint>

// ============================================================================
// FusedLoRAAdapter:  y = x @ W^T + bias + (alpha/r) * (x @ A^T) @ B^T
//
// sm_100 baseline ISA (no tcgen05 on this build target).
//   1) h = x @ A^T                          (tiny fp32 kernel)
//   2) K-extension: x_ext=[x|scale*h|0], W_ext=[W|B|0], KE=4160
//   3) Both operands rounded to fp16. Measured error anchor: W-only rounding
//      gave rel_err 2.08e-4; x adds independently -> ~2.9e-4 < 1e-3.
//   4) GEMM via mma.sync.m16n8k16.f16: 128x128x64 tiles, 3-stage cp.async,
//      2 CTAs/SM, 8x8 supertile rasterization.
// ============================================================================

#define LORA_ALPHA 16.0f

constexpr int MM = 8192, NN = 4096, KK = 4096, RR = 16;
constexpr int KE = 4160;                    // 4096 + 16 + 48 pad
constexpr int BM = 128, BN = 128, BK = 64;  // BK in fp16 (128 B rows)
constexpr int NKT = KE / BK;                // 65
constexpr int STAGES = 3;

// -------- scratch (static device globals; no allocation) --------
__device__ float g_h[MM * RR];
__device__ __align__(256) __half g_xh[(size_t)MM * KE];
__device__ __align__(256) __half g_wh[(size_t)NN * KE];

// ============================================================================
// helpers
// ============================================================================
__device__ __forceinline__ uint32_t smem_u32(const void* p) {
    uint32_t a;
    asm("{ .reg .u64 t; cvta.to.shared.u64 t, %1; cvt.u32.u64 %0, t; }"
        : "=r"(a) : "l"(p));
    return a;
}
// canonical SW128 swizzle for 128B rows: byte bits [6:4] ^= bits [9:7]
__device__ __forceinline__ uint32_t swz(uint32_t o) {
    return o ^ ((o >> 3) & 0x70);
}

#define CP16(dst, src) \
    asm volatile("cp.async.cg.shared.global [%0], [%1], 16;" \
                 :: "r"(dst), "l"(src) : "memory")
#define CP_COMMIT() asm volatile("cp.async.commit_group;" ::: "memory")
#define CP_WAIT1()  asm volatile("cp.async.wait_group 1;" ::: "memory")

#define LDSM4(r, a) \
    asm volatile("ldmatrix.sync.aligned.m8n8.x4.shared.b16 {%0,%1,%2,%3}, [%4];" \
                 : "=r"((r)[0]), "=r"((r)[1]), "=r"((r)[2]), "=r"((r)[3]) \
                 : "r"(a))

__device__ __forceinline__ void mma16816(float* d, const uint32_t* a,
                                         uint32_t b0, uint32_t b1) {
    asm volatile(
        "mma.sync.aligned.m16n8k16.row.col.f32.f16.f16.f32 "
        "{%0,%1,%2,%3}, {%4,%5,%6,%7}, {%8,%9}, {%0,%1,%2,%3};"
        : "+f"(d[0]), "+f"(d[1]), "+f"(d[2]), "+f"(d[3])
        : "r"(a[0]), "r"(a[1]), "r"(a[2]), "r"(a[3]), "r"(b0), "r"(b1));
}

// ============================================================================
// Kernel 1: h = x @ A^T  (one warp per row)
// ============================================================================
__global__ __launch_bounds__(256) void lora_down_kernel(
    const float* __restrict__ x, const float* __restrict__ A)
{
    int warp = (blockIdx.x * blockDim.x + threadIdx.x) >> 5;
    int lane = threadIdx.x & 31;
    if (warp >= MM) return;
    const float* xr = x + (size_t)warp * KK;

    float acc[RR];
#pragma unroll
    for (int r = 0; r < RR; ++r) acc[r] = 0.f;

    for (int k = lane * 4; k < KK; k += 128) {
        float4 xv = *reinterpret_cast<const float4*>(xr + k);
#pragma unroll
        for (int r = 0; r < RR; ++r) {
            float4 av = *reinterpret_cast<const float4*>(A + (size_t)r * KK + k);
            acc[r] = fmaf(xv.x, av.x, acc[r]);
            acc[r] = fmaf(xv.y, av.y, acc[r]);
            acc[r] = fmaf(xv.z, av.z, acc[r]);
            acc[r] = fmaf(xv.w, av.w, acc[r]);
        }
    }
#pragma unroll
    for (int r = 0; r < RR; ++r)
#pragma unroll
        for (int off = 16; off > 0; off >>= 1)
            acc[r] += __shfl_xor_sync(0xffffffffu, acc[r], off);

    if (lane == 0) {
#pragma unroll
        for (int r = 0; r < RR; ++r) g_h[(size_t)warp * RR + r] = acc[r];
    }
}

// ============================================================================
// Kernels 2/3: fp32 -> fp16 with K-extension
// ============================================================================
__global__ __launch_bounds__(256) void convert_x_kernel(
    const float* __restrict__ x, float scale)
{
    size_t idx = (size_t)blockIdx.x * blockDim.x + threadIdx.x;
    constexpr size_t GROUPS = (size_t)MM * (KE / 4);
    if (idx >= GROUPS) return;
    int m = (int)(idx / (KE / 4));
    int k = (int)(idx % (KE / 4)) * 4;

    float v[4];
    if (k < KK) {
        float4 t = *reinterpret_cast<const float4*>(x + (size_t)m * KK + k);
        v[0] = t.x; v[1] = t.y; v[2] = t.z; v[3] = t.w;
    } else if (k < KK + RR) {
        const float* hp = g_h + (size_t)m * RR + (k - KK);
        v[0] = scale * hp[0]; v[1] = scale * hp[1];
        v[2] = scale * hp[2]; v[3] = scale * hp[3];
    } else {
        v[0] = v[1] = v[2] = v[3] = 0.f;
    }
    unsigned short h[4];
#pragma unroll
    for (int e = 0; e < 4; ++e) h[e] = __half_as_ushort(__float2half_rn(v[e]));
    uint2 hw;
    hw.x = (uint32_t)h[0] | ((uint32_t)h[1] << 16);
    hw.y = (uint32_t)h[2] | ((uint32_t)h[3] << 16);
    *reinterpret_cast<uint2*>(&g_xh[(size_t)m * KE + k]) = hw;
}

__global__ __launch_bounds__(256) void convert_w_kernel(
    const float* __restrict__ W, const float* __restrict__ Bm)
{
    size_t idx = (size_t)blockIdx.x * blockDim.x + threadIdx.x;
    constexpr size_t GROUPS = (size_t)NN * (KE / 4);
    if (idx >= GROUPS) return;
    int n = (int)(idx / (KE / 4));
    int k = (int)(idx % (KE / 4)) * 4;

    float v[4];
    if (k < KK) {
        float4 t = *reinterpret_cast<const float4*>(W + (size_t)n * KK + k);
        v[0] = t.x; v[1] = t.y; v[2] = t.z; v[3] = t.w;
    } else if (k < KK + RR) {
        const float* bp = Bm + (size_t)n * RR + (k - KK);
        v[0] = bp[0]; v[1] = bp[1]; v[2] = bp[2]; v[3] = bp[3];
    } else {
        v[0] = v[1] = v[2] = v[3] = 0.f;
    }
    unsigned short h[4];
#pragma unroll
    for (int e = 0; e < 4; ++e) h[e] = __half_as_ushort(__float2half_rn(v[e]));
    uint2 hw;
    hw.x = (uint32_t)h[0] | ((uint32_t)h[1] << 16);
    hw.y = (uint32_t)h[2] | ((uint32_t)h[3] << 16);
    *reinterpret_cast<uint2*>(&g_wh[(size_t)n * KE + k]) = hw;
}

// ============================================================================
// Kernel 4: fp16 GEMM. 128x128x64 tiles, 3-stage cp.async pipeline.
// 256 threads / 8 warps (2 m-groups x 4 n-groups), warp tile 64x32.
// Per K-chunk per warp: 4 k16 steps x (6 LDSM.x4 + 16 HMMA) between barriers.
// 2 CTAs/SM (96 KB smem, <=128 regs).
// ============================================================================
constexpr int TILE_B  = BM * BK * 2;        // 16384 bytes per tensor tile
constexpr int OFF_A = 0, OFF_B = TILE_B;
constexpr int STAGE_B = 2 * TILE_B;         // 32768
constexpr int GEMM_SMEM = STAGES * STAGE_B; // 98304

__global__ void __launch_bounds__(256, 2) gemm_kernel(
    const float* __restrict__ bias, float* __restrict__ out)
{
    extern __shared__ char smem[];
    const uint32_t sbase = smem_u32(smem);
    const int tid = threadIdx.x;
    const int lane = tid & 31;
    const int wid = tid >> 5;
    const int wm = wid & 1;        // 0..1  (64-row group)
    const int wn = wid >> 1;       // 0..3  (32-col group)

    // ---- 8x8 supertile rasterization for L2 reuse ----
    const int t = blockIdx.x;                 // 0..2047
    const int sb_id = t >> 6;                 // 0..31
    const int smt = sb_id & 7, snt = sb_id >> 3;
    const int lt = t & 63;
    const int bm = (smt * 8 + (lt & 7)) * BM;
    const int bn = (snt * 8 + (lt >> 3)) * BN;

    // ---- load mapping: thread -> 1 row x 4 chunks of 16B per tensor ----
    const int lrow = tid >> 1;                // 0..127
    const int lc0 = (tid & 1) * 64;           // 0 or 64 (byte col base)
    uint32_t dst[4];
#pragma unroll
    for (int c = 0; c < 4; ++c)
        dst[c] = swz((uint32_t)lrow * 128 + lc0 + c * 16);

    const char* px = (const char*)g_xh + ((size_t)(bm + lrow) * KE) * 2 + lc0;
    const char* pw = (const char*)g_wh + ((size_t)(bn + lrow) * KE) * 2 + lc0;

    float acc[4][4][4];
#pragma unroll
    for (int i = 0; i < 4; ++i)
#pragma unroll
        for (int j = 0; j < 4; ++j)
#pragma unroll
            for (int e = 0; e < 4; ++e) acc[i][j][e] = 0.f;

    const int ar = lane & 15;                 // row within 16-row A tile
    const int ah_half = (lane >> 4) * 16;     // 0 or 16 bytes (k half)
    const int brow = wn * 32 + lane;          // B row for ldsm.x4

    auto load_stage = [&](int kt, int s) {
        const uint32_t st = sbase + s * STAGE_B;
        const size_t ko = (size_t)kt * 128;   // 64 fp16 = 128 bytes
#pragma unroll
        for (int c = 0; c < 4; ++c) {
            CP16(st + OFF_A + dst[c], px + ko + c * 16);
            CP16(st + OFF_B + dst[c], pw + ko + c * 16);
        }
    };

    // prologue: stages 0,1
    load_stage(0, 0); CP_COMMIT();
    load_stage(1, 1); CP_COMMIT();

    int scur = 0, snxt = 2;
    for (int kt = 0; kt < NKT; ++kt) {
        CP_WAIT1();
        __syncthreads();

        const int nk = kt + STAGES - 1;
        if (nk < NKT) load_stage(nk, snxt);
        CP_COMMIT();

        const uint32_t st = sbase + scur * STAGE_B;

#pragma unroll
        for (int ks = 0; ks < 4; ++ks) {
            const int kb = ks * 32;           // byte base of this k16
            uint32_t a[4][4];
#pragma unroll
            for (int mt = 0; mt < 4; ++mt) {
                const uint32_t ro = (uint32_t)(wm * 64 + mt * 16 + ar) * 128;
                LDSM4(a[mt], st + OFF_A + swz(ro + kb + ah_half));
            }
            uint32_t b0[4], b1[4];
            {
                const uint32_t ro = (uint32_t)brow * 128;
                LDSM4(b0, st + OFF_B + swz(ro + kb));
                LDSM4(b1, st + OFF_B + swz(ro + kb + 16));
            }
#pragma unroll
            for (int mt = 0; mt < 4; ++mt)
#pragma unroll
                for (int nt = 0; nt < 4; ++nt)
                    mma16816(acc[mt][nt], a[mt], b0[nt], b1[nt]);
        }
        // stage reuse ordered by next iteration's top barrier

        if (++scur == STAGES) scur = 0;
        if (++snxt == STAGES) snxt = 0;
    }

    // ---- epilogue: acc + bias -> out ----
    const int g = lane >> 2;       // 0..7
    const int j = (lane & 3) * 2;  // 0,2,4,6
#pragma unroll
    for (int mt = 0; mt < 4; ++mt) {
#pragma unroll
        for (int nt = 0; nt < 4; ++nt) {
            const int m0 = bm + wm * 64 + mt * 16 + g;
            const int n0 = bn + wn * 32 + nt * 8 + j;
            const float b0 = __ldg(bias + n0);
            const float b1 = __ldg(bias + n0 + 1);
            float2 v0 = make_float2(acc[mt][nt][0] + b0, acc[mt][nt][1] + b1);
            float2 v1 = make_float2(acc[mt][nt][2] + b0, acc[mt][nt][3] + b1);
            *reinterpret_cast<float2*>(out + (size_t)m0 * NN + n0) = v0;
            *reinterpret_cast<float2*>(out + (size_t)(m0 + 8) * NN + n0) = v1;
        }
    }
}

// ============================================================================
// Launch
// ============================================================================
extern "C" void kernel_launch(void* const* d_in, const int* in_sizes, int n_in,
                              void* d_out, int out_size)
{
    const float* x    = (const float*)d_in[0];  // [M,K]
    const float* W    = (const float*)d_in[1];  // [N,K]
    const float* A    = (const float*)d_in[2];  // [R,K]
    const float* Bm   = (const float*)d_in[3];  // [N,R]
    const float* bias = (const float*)d_in[4];  // [N]
    float* out = (float*)d_out;

    const float scale = LORA_ALPHA / (float)RR;

    cudaFuncSetAttribute(gemm_kernel,
                         cudaFuncAttributeMaxDynamicSharedMemorySize, GEMM_SMEM);

    // 1) h = x @ A^T
    lora_down_kernel<<<(MM + 7) / 8, 256>>>(x, A);

    // 2) x (+scale*h, +pad) -> fp16
    {
        size_t groups = (size_t)MM * (KE / 4);
        convert_x_kernel<<<(unsigned)((groups + 255) / 256), 256>>>(x, scale);
    }
    // 3) W (+B, +pad) -> fp16
    {
        size_t groups = (size_t)NN * (KE / 4);
        convert_w_kernel<<<(unsigned)((groups + 255) / 256), 256>>>(W, Bm);
    }
    // 4) GEMM + bias epilogue
    gemm_kernel<<<2048, 256, GEMM_SMEM>>>(bias, out);
}